// round 15
// baseline (speedup 1.0000x reference)
#include <cuda_runtime.h>

#define TPB 256
#define PAD_A 68   // staging/A pad (float4-aligned, phase-conflict-free)
#define PAD_C 65   // C pad (odd: conflict-free row+col scalar access)
#define PAD_G 67
// buf (256*PAD_A overlay for A and C) + sB + sG + small vectors
#define SMEM_FLOATS (256*PAD_A + 64*PAD_A + 64*PAD_G + 64*5 + 128)
#define SMEM_BYTES (SMEM_FLOATS * 4)

__device__ __forceinline__ unsigned long long pk2(float x, float y) {
    unsigned long long r;
    asm("mov.b64 %0, {%1, %2};" : "=l"(r) : "f"(x), "f"(y));
    return r;
}
__device__ __forceinline__ void upk2(unsigned long long v, float &x, float &y) {
    asm("mov.b64 {%0, %1}, %2;" : "=f"(x), "=f"(y) : "l"(v));
}
__device__ __forceinline__ void fma2(unsigned long long &d, unsigned long long a, unsigned long long b) {
    asm("fma.rn.f32x2 %0, %1, %2, %0;" : "+l"(d) : "l"(a), "l"(b));
}

__global__ void __launch_bounds__(TPB, 2) conn_kernel(
    const float* __restrict__ x, const float* __restrict__ v,
    const float* __restrict__ W1, const float* __restrict__ b1,
    const float* __restrict__ W2, const float* __restrict__ b2g,
    const float* __restrict__ W3, float* __restrict__ out)
{
    const int n = blockIdx.x;
    const int t = threadIdx.x;

    extern __shared__ float smem[];
    float* buf = smem;                    // overlay: sA [256][PAD_A] / sC [256][PAD_C]
    float* sB  = buf + 256 * PAD_A;       // [64][PAD_A]  B[m][l] = s[m]*W1[m][l]
    float* sG  = sB  + 64 * PAD_A;        // [64][PAD_G]  g augmented (col 64 = rhs)
    float* sh  = sG  + 64 * PAD_G;        // h
    float* sv  = sh  + 64;                // v row
    float* sx  = sv  + 64;                // x row
    float* ssc = sx  + 64;                // s = 1 - h^2
    float* sf  = ssc + 64;                // GJ factors
    float* sz  = sf  + 64;                // [128] concat(v, dv)

    // ---- load x, v ----
    if (t < 64) { sx[t] = x[n*64 + t]; sv[t] = v[n*64 + t]; }
    __syncthreads();

    // ---- h = tanh(W1 x + b1), s = 1 - h^2 ----
    {
        const int m = t >> 2, q = t & 3;
        const float4* w1r = (const float4*)(W1 + m*64 + q*16);
        float p = 0.f;
        #pragma unroll
        for (int k = 0; k < 4; k++) {
            float4 wv = w1r[k];
            const float* xs = sx + q*16 + k*4;
            p += wv.x*xs[0] + wv.y*xs[1] + wv.z*xs[2] + wv.w*xs[3];
        }
        p += __shfl_xor_sync(0xffffffffu, p, 1);
        p += __shfl_xor_sync(0xffffffffu, p, 2);
        if (q == 0) {
            float hh = tanhf(p + b1[m]);
            sh[m]  = hh;
            ssc[m] = 1.f - hh*hh;
        }
    }
    __syncthreads();

    // ---- sB[m][l] = s[m] * W1[m][l] ----
    {
        const int m = t >> 2, q = t & 3;
        const float sm_ = ssc[m];
        const float4* w1r = (const float4*)(W1 + m*64 + q*16);
        float4* dst = (float4*)(sB + m*PAD_A + q*16);
        #pragma unroll
        for (int k = 0; k < 4; k++) {
            float4 wv = w1r[k];
            wv.x *= sm_; wv.y *= sm_; wv.z *= sm_; wv.w *= sm_;
            dst[k] = wv;
        }
    }
    // (first stage __syncthreads orders sB before GEMM reads)

    const int tx = t & 7;       // GEMM col group (0..7): cols {4tx..} and {32+4tx..}
    const int ty = t >> 3;      // GEMM row base (0..31): rows ty + 32a
    const int rr = t & 63;      // stage row index
    const int pp = t >> 6;      // stage block index
    const int ll = t & 63;      // consume: l index (fixed per thread)
    const int jp = t >> 6;      // consume: j-part (0..3)

    // single-register w accumulator: w_l partial over this thread's 16 j's
    float waccl = 0.f;

    const float* bcol0 = sB + 4*tx;        // B column base (low half)
    const float* arow0 = buf + ty*PAD_A;   // A row base

    // ============ group loop: 4 bb blocks per iteration ============
    for (int g = 0; g < 16; ++g) {
        const int bb0 = g * 4;

        // ---- stage 4 Wsym blocks into buf-as-A; fuse g-column dot with h ----
        {
            const int u = pp, r = rr;
            const int bb = bb0 + u;
            const float4* p1 = (const float4*)(W2 + (bb*64 + r)*64);
            const float4* p2 = (const float4*)(W2 + (r*64 + bb)*64);
            float* dst = buf + (u*64 + r)*PAD_A;
            float gp = 0.f;
            #pragma unroll
            for (int k = 0; k < 16; ++k) {
                float4 a1 = p1[k];
                float4 a2 = p2[k];
                a1.x += a2.x; a1.y += a2.y; a1.z += a2.z; a1.w += a2.w;
                *(float4*)(dst + 4*k) = a1;
                const float* hp = sh + 4*k;
                gp += a1.x*hp[0] + a1.y*hp[1] + a1.z*hp[2] + a1.w*hp[3];
            }
            sG[r*PAD_G + bb] = gp + b2g[bb*64 + r] + b2g[r*64 + bb];
        }
        __syncthreads();

        // ---- GEMM: Cstack(256x64) = Astack(256x64) @ B(64x64), 8x8 tile/thread ----
        unsigned long long acc[8][4];
        #pragma unroll
        for (int a = 0; a < 8; ++a) {
            acc[a][0] = 0ull; acc[a][1] = 0ull; acc[a][2] = 0ull; acc[a][3] = 0ull;
        }

        #pragma unroll 1
        for (int m2 = 0; m2 < 64; m2 += 2) {
            float2 av8[8];
            #pragma unroll
            for (int a = 0; a < 8; ++a)
                av8[a] = *(const float2*)(arow0 + (32*a)*PAD_A + m2);
            const float* b0p = bcol0 + m2*PAD_A;
            const ulonglong2 b0l = *(const ulonglong2*)(b0p);
            const ulonglong2 b0h = *(const ulonglong2*)(b0p + 32);
            const ulonglong2 b1l = *(const ulonglong2*)(b0p + PAD_A);
            const ulonglong2 b1h = *(const ulonglong2*)(b0p + PAD_A + 32);
            #pragma unroll
            for (int a = 0; a < 8; ++a) {
                const unsigned long long a0 = pk2(av8[a].x, av8[a].x);
                fma2(acc[a][0], a0, b0l.x);
                fma2(acc[a][1], a0, b0l.y);
                fma2(acc[a][2], a0, b0h.x);
                fma2(acc[a][3], a0, b0h.y);
                const unsigned long long a1 = pk2(av8[a].y, av8[a].y);
                fma2(acc[a][0], a1, b1l.x);
                fma2(acc[a][1], a1, b1l.y);
                fma2(acc[a][2], a1, b1h.x);
                fma2(acc[a][3], a1, b1h.y);
            }
        }
        __syncthreads();   // everyone done reading buf-as-A

        // ---- store C into buf-as-C (pad 65, scalar stores: phase-conflict-free) ----
        #pragma unroll
        for (int a = 0; a < 8; ++a) {
            float* crow = buf + (ty + 32*a)*PAD_C;
            float f0, f1;
            upk2(acc[a][0], f0, f1); crow[4*tx]      = f0; crow[4*tx + 1]      = f1;
            upk2(acc[a][1], f0, f1); crow[4*tx + 2]  = f0; crow[4*tx + 3]      = f1;
            upk2(acc[a][2], f0, f1); crow[32 + 4*tx] = f0; crow[32 + 4*tx + 1] = f1;
            upk2(acc[a][3], f0, f1); crow[32 + 4*tx + 2] = f0; crow[32 + 4*tx + 3] = f1;
        }
        __syncthreads();

        // ---- consume (transposed mapping): thread owns l=ll, sums 16 j's ----
        //   waccl += v_i v_j C[j][ll]^2 C[ll][j], blocks i = bb0..bb0+3
        #pragma unroll
        for (int u = 0; u < 4; ++u) {
            const float vi = sv[bb0 + u];
            const float* ccol = buf + (u*64 + jp*16)*PAD_C + ll;  // C[j][ll], j stride
            const float* crow = buf + (u*64 + ll)*PAD_C + jp*16;  // C[ll][j]
            #pragma unroll
            for (int jj = 0; jj < 16; ++jj) {
                const float c  = ccol[jj*PAD_C];
                const float ct = crow[jj];
                waccl += vi * sv[jp*16 + jj] * c * c * ct;
            }
        }
        __syncthreads();   // before next stage overwrites buf
    }

    // ---- reduce 4 j-parts per l into rhs column of sG (buf as scratch) ----
    buf[jp*64 + ll] = waccl;
    __syncthreads();
    if (t < 64) {
        sG[t*PAD_G + 64] = buf[t] + buf[64 + t] + buf[128 + t] + buf[192 + t];
    }
    __syncthreads();

    // ---- Gauss-Jordan solve g y = w  (g SPD-ish, no pivoting) ----
    {
        const int r    = t & 63;
        const int part = t >> 6;
        const int cbeg = part * 16;
        for (int p = 0; p < 64; p++) {
            if (t < 64) {
                const float piv = sG[p*PAD_G + p];
                sf[t] = (t == p) ? 0.f : sG[t*PAD_G + p] / piv;
            }
            __syncthreads();
            if (r != p) {
                const float fr = sf[r];
                const float* prow = sG + p*PAD_G;
                float* rrow = sG + r*PAD_G;
                #pragma unroll
                for (int c = 0; c < 16; c++)
                    rrow[cbeg + c] -= fr * prow[cbeg + c];
                if (part == 3)
                    rrow[64] -= fr * prow[64];
            }
            __syncthreads();
        }
    }

    // ---- dv = 0.5 * y ; z = concat(v, dv) ----
    if (t < 64) {
        const float y = sG[t*PAD_G + 64] / sG[t*PAD_G + t];
        sz[t]      = sv[t];
        sz[64 + t] = 0.5f * y;
    }
    __syncthreads();

    // ---- out[n,k] = sum_c z[c] * W3[k, c] ----
    {
        const int k = t >> 2, q = t & 3;
        const float4* w3r = (const float4*)(W3 + k*128 + q*32);
        float p = 0.f;
        #pragma unroll
        for (int j = 0; j < 8; j++) {
            float4 wv = w3r[j];
            const float* zz = sz + q*32 + j*4;
            p += wv.x*zz[0] + wv.y*zz[1] + wv.z*zz[2] + wv.w*zz[3];
        }
        p += __shfl_xor_sync(0xffffffffu, p, 1);
        p += __shfl_xor_sync(0xffffffffu, p, 2);
        if (q == 0) out[n*64 + k] = p;
    }
}

extern "C" void kernel_launch(void* const* d_in, const int* in_sizes, int n_in,
                              void* d_out, int out_size)
{
    // inputs: 0:t (unused), 1:x (256*64), 2:v, 3:W1, 4:b1, 5:W2 (4096*64),
    //         6:b2 (4096), 7:W3 (64*128); output: (256,64) fp32
    const float* x  = (const float*)d_in[1];
    const float* v  = (const float*)d_in[2];
    const float* W1 = (const float*)d_in[3];
    const float* b1 = (const float*)d_in[4];
    const float* W2 = (const float*)d_in[5];
    const float* b2 = (const float*)d_in[6];
    const float* W3 = (const float*)d_in[7];

    cudaFuncSetAttribute(conn_kernel,
                         cudaFuncAttributeMaxDynamicSharedMemorySize, SMEM_BYTES);
    conn_kernel<<<256, TPB, SMEM_BYTES>>>(x, v, W1, b1, W2, b2, W3, (float*)d_out);
}

// round 16
// speedup vs baseline: 1.6761x; 1.6761x over previous
#include <cuda_runtime.h>

// ================= kernel A: per half-sample GEMM + w/g production =========
#define PAD_A 68
#define PAD_C 65
#define PAD_G 67

// smem: buf 128*PAD_A + sB 64*PAD_A + 4 small vectors
#define KA_SMEM_FLOATS (128*PAD_A + 64*PAD_A + 64*4)
#define KA_SMEM_BYTES (KA_SMEM_FLOATS * 4)

#define KB_SMEM_FLOATS (64*PAD_G + 64 + 128 + 64)
#define KB_SMEM_BYTES (KB_SMEM_FLOATS * 4)

static __device__ float g_g[256][64][64];   // [n][i][r] = g[r][i]
static __device__ float g_w[512][64];       // per half-CTA partial w

__device__ __forceinline__ unsigned long long pk2(float x, float y) {
    unsigned long long r;
    asm("mov.b64 %0, {%1, %2};" : "=l"(r) : "f"(x), "f"(y));
    return r;
}
__device__ __forceinline__ void upk2(unsigned long long v, float &x, float &y) {
    asm("mov.b64 {%0, %1}, %2;" : "=f"(x), "=f"(y) : "l"(v));
}
__device__ __forceinline__ void fma2(unsigned long long &d, unsigned long long a, unsigned long long b) {
    asm("fma.rn.f32x2 %0, %1, %2, %0;" : "+l"(d) : "l"(a), "l"(b));
}

__global__ void __launch_bounds__(128, 4) connA_kernel(
    const float* __restrict__ x, const float* __restrict__ v,
    const float* __restrict__ W1, const float* __restrict__ b1,
    const float* __restrict__ W2, const float* __restrict__ b2g)
{
    const int c    = blockIdx.x;
    const int n    = c >> 1;
    const int half = c & 1;
    const int t    = threadIdx.x;

    extern __shared__ float smem[];
    float* buf = smem;                 // overlay: A [128][PAD_A] / C [128][PAD_C] / scratch
    float* sB  = buf + 128 * PAD_A;    // [64][PAD_A]
    float* sh  = sB  + 64 * PAD_A;
    float* sv  = sh  + 64;
    float* sx  = sv  + 64;
    float* ssc = sx  + 64;

    // ---- load x, v ----
    if (t < 64) { sx[t] = x[n*64 + t]; sv[t] = v[n*64 + t]; }
    __syncthreads();

    // ---- h = tanh(W1 x + b1), s = 1 - h^2  (2 threads per row) ----
    const int m  = t >> 1;
    const int qq = t & 1;
    {
        const float4* w1r = (const float4*)(W1 + m*64 + qq*32);
        float p = 0.f;
        #pragma unroll
        for (int k = 0; k < 8; k++) {
            float4 wv = w1r[k];
            const float* xs = sx + qq*32 + k*4;
            p += wv.x*xs[0] + wv.y*xs[1] + wv.z*xs[2] + wv.w*xs[3];
        }
        p += __shfl_xor_sync(0xffffffffu, p, 1);
        if (qq == 0) {
            float hh = tanhf(p + b1[m]);
            sh[m]  = hh;
            ssc[m] = 1.f - hh*hh;
        }
    }
    __syncthreads();

    // ---- sB[m][l] = s[m] * W1[m][l]  (2 threads per row, 32 cols each) ----
    {
        const float sm_ = ssc[m];
        const float4* w1r = (const float4*)(W1 + m*64 + qq*32);
        float4* dst = (float4*)(sB + m*PAD_A + qq*32);
        #pragma unroll
        for (int k = 0; k < 8; k++) {
            float4 wv = w1r[k];
            wv.x *= sm_; wv.y *= sm_; wv.z *= sm_; wv.w *= sm_;
            dst[k] = wv;
        }
    }
    // (first group's stage __syncthreads orders sB before GEMM reads)

    float wacc[16];
    #pragma unroll
    for (int k = 0; k < 16; k++) wacc[k] = 0.f;

    const int tx = t & 7;        // GEMM col group
    const int ty = t >> 3;       // GEMM row base (0..15), rows ty + 16a
    const int ur = t >> 6;       // stage block (0..1)
    const int rr = t & 63;       // stage row
    const int j2 = t & 31;       // consume j base (j2, j2+32)
    const int pq = t >> 5;       // consume l-quarter (0..3) == warp id

    const float* bcol0 = sB + 4*tx;
    const float* arow0 = buf + ty*PAD_A;

    // ============ group loop: 2 bb blocks per iteration, 16 groups ============
    for (int g = 0; g < 16; ++g) {
        const int bb0 = half*32 + g*2;

        // ---- stage 2 Wsym blocks into buf-as-A; fused g-column dot ----
        {
            const int bb = bb0 + ur;
            const float4* p1 = (const float4*)(W2 + (bb*64 + rr)*64);
            const float4* p2 = (const float4*)(W2 + (rr*64 + bb)*64);
            float* dst = buf + (ur*64 + rr)*PAD_A;
            float gp = 0.f;
            #pragma unroll
            for (int k = 0; k < 16; ++k) {
                float4 a1 = p1[k];
                float4 a2 = p2[k];
                a1.x += a2.x; a1.y += a2.y; a1.z += a2.z; a1.w += a2.w;
                *(float4*)(dst + 4*k) = a1;
                const float* hp = sh + 4*k;
                gp += a1.x*hp[0] + a1.y*hp[1] + a1.z*hp[2] + a1.w*hp[3];
            }
            g_g[n][bb][rr] = gp + b2g[bb*64 + rr] + b2g[rr*64 + bb];
        }
        __syncthreads();

        // ---- GEMM: C(128x64) = A(128x64) @ B(64x64), 8x8 tile/thread ----
        unsigned long long acc[8][4];
        #pragma unroll
        for (int a = 0; a < 8; ++a) {
            acc[a][0] = 0ull; acc[a][1] = 0ull; acc[a][2] = 0ull; acc[a][3] = 0ull;
        }

        #pragma unroll 1
        for (int m2 = 0; m2 < 64; m2 += 2) {
            float2 av8[8];
            #pragma unroll
            for (int a = 0; a < 8; ++a)
                av8[a] = *(const float2*)(arow0 + (16*a)*PAD_A + m2);
            const float* b0p = bcol0 + m2*PAD_A;
            const float4 bl0 = *(const float4*)(b0p);
            const float4 bh0 = *(const float4*)(b0p + 32);
            const float4 bl1 = *(const float4*)(b0p + PAD_A);
            const float4 bh1 = *(const float4*)(b0p + PAD_A + 32);
            const unsigned long long b00 = pk2(bl0.x, bl0.y);
            const unsigned long long b01 = pk2(bl0.z, bl0.w);
            const unsigned long long b02 = pk2(bh0.x, bh0.y);
            const unsigned long long b03 = pk2(bh0.z, bh0.w);
            const unsigned long long b10 = pk2(bl1.x, bl1.y);
            const unsigned long long b11 = pk2(bl1.z, bl1.w);
            const unsigned long long b12 = pk2(bh1.x, bh1.y);
            const unsigned long long b13 = pk2(bh1.z, bh1.w);
            #pragma unroll
            for (int a = 0; a < 8; ++a) {
                const unsigned long long a0 = pk2(av8[a].x, av8[a].x);
                fma2(acc[a][0], a0, b00);
                fma2(acc[a][1], a0, b01);
                fma2(acc[a][2], a0, b02);
                fma2(acc[a][3], a0, b03);
                const unsigned long long a1 = pk2(av8[a].y, av8[a].y);
                fma2(acc[a][0], a1, b10);
                fma2(acc[a][1], a1, b11);
                fma2(acc[a][2], a1, b12);
                fma2(acc[a][3], a1, b13);
            }
        }
        __syncthreads();   // done reading buf-as-A

        // ---- store C into buf-as-C (pad 65) ----
        #pragma unroll
        for (int a = 0; a < 8; ++a) {
            float* crow = buf + (ty + 16*a)*PAD_C;
            float f0, f1;
            upk2(acc[a][0], f0, f1); crow[4*tx]      = f0; crow[4*tx + 1]      = f1;
            upk2(acc[a][1], f0, f1); crow[4*tx + 2]  = f0; crow[4*tx + 3]      = f1;
            upk2(acc[a][2], f0, f1); crow[32 + 4*tx] = f0; crow[32 + 4*tx + 1] = f1;
            upk2(acc[a][3], f0, f1); crow[32 + 4*tx + 2] = f0; crow[32 + 4*tx + 3] = f1;
        }
        __syncthreads();

        // ---- consume: thread = (j2, quarter pq); j in {j2, j2+32}, both blocks ----
        #pragma unroll
        for (int u = 0; u < 2; ++u) {
            const float vi = sv[bb0 + u];
            #pragma unroll
            for (int jh = 0; jh < 2; ++jh) {
                const int j = j2 + jh*32;
                const float coef = vi * sv[j];
                const float* crow = buf + (u*64 + j)*PAD_C;        // C[j][l]
                const float* ccol = buf + (u*64)*PAD_C + j;        // C[l][j] base
                #pragma unroll
                for (int k = 0; k < 16; ++k) {
                    const int l = pq*16 + k;
                    const float cc = crow[l];
                    const float ct = ccol[l*PAD_C];
                    wacc[k] += coef * cc * cc * ct;
                }
            }
        }
        __syncthreads();   // before next stage overwrites buf
    }

    // ---- reduce: scratch[j2][l], sum over j2, write partial w ----
    #pragma unroll
    for (int k = 0; k < 16; ++k) buf[j2*PAD_C + pq*16 + k] = wacc[k];
    __syncthreads();
    if (t < 64) {
        float s = 0.f;
        #pragma unroll 4
        for (int j = 0; j < 32; ++j) s += buf[j*PAD_C + t];
        g_w[c][t] = s;
    }
}

// ================= kernel B: assemble g, solve, output ======================
__global__ void __launch_bounds__(256, 4) connB_kernel(
    const float* __restrict__ v, const float* __restrict__ W3,
    float* __restrict__ out)
{
    const int n = blockIdx.x;
    const int t = threadIdx.x;

    extern __shared__ float smem[];
    float* sG = smem;               // [64][PAD_G], col 64 = rhs
    float* sf = sG + 64*PAD_G;
    float* sz = sf + 64;            // [128]
    float* sv = sz + 128;

    // load g: g_g[n][i][r] holds g[r][i]
    for (int idx = t; idx < 4096; idx += 256) {
        const int i = idx >> 6, r = idx & 63;
        sG[r*PAD_G + i] = g_g[n][i][r];
    }
    if (t < 64) {
        sG[t*PAD_G + 64] = g_w[2*n][t] + g_w[2*n + 1][t];
        sv[t] = v[n*64 + t];
    }
    __syncthreads();

    // Gauss-Jordan solve g y = w
    {
        const int r    = t & 63;
        const int part = t >> 6;
        const int cbeg = part * 16;
        for (int p = 0; p < 64; p++) {
            if (t < 64) {
                const float piv = sG[p*PAD_G + p];
                sf[t] = (t == p) ? 0.f : sG[t*PAD_G + p] / piv;
            }
            __syncthreads();
            if (r != p) {
                const float fr = sf[r];
                const float* prow = sG + p*PAD_G;
                float* rrow = sG + r*PAD_G;
                #pragma unroll
                for (int cc = 0; cc < 16; cc++)
                    rrow[cbeg + cc] -= fr * prow[cbeg + cc];
                if (part == 3)
                    rrow[64] -= fr * prow[64];
            }
            __syncthreads();
        }
    }

    if (t < 64) {
        const float y = sG[t*PAD_G + 64] / sG[t*PAD_G + t];
        sz[t]      = sv[t];
        sz[64 + t] = 0.5f * y;
    }
    __syncthreads();

    // out[n,k] = sum_c z[c] * W3[k, c]
    {
        const int k = t >> 2, q = t & 3;
        const float4* w3r = (const float4*)(W3 + k*128 + q*32);
        float p = 0.f;
        #pragma unroll
        for (int j = 0; j < 8; j++) {
            float4 wv = w3r[j];
            const float* zz = sz + q*32 + j*4;
            p += wv.x*zz[0] + wv.y*zz[1] + wv.z*zz[2] + wv.w*zz[3];
        }
        p += __shfl_xor_sync(0xffffffffu, p, 1);
        p += __shfl_xor_sync(0xffffffffu, p, 2);
        if (q == 0) out[n*64 + k] = p;
    }
}

extern "C" void kernel_launch(void* const* d_in, const int* in_sizes, int n_in,
                              void* d_out, int out_size)
{
    // inputs: 0:t (unused), 1:x (256*64), 2:v, 3:W1, 4:b1, 5:W2 (4096*64),
    //         6:b2 (4096), 7:W3 (64*128); output: (256,64) fp32
    const float* x  = (const float*)d_in[1];
    const float* v  = (const float*)d_in[2];
    const float* W1 = (const float*)d_in[3];
    const float* b1 = (const float*)d_in[4];
    const float* W2 = (const float*)d_in[5];
    const float* b2 = (const float*)d_in[6];
    const float* W3 = (const float*)d_in[7];

    cudaFuncSetAttribute(connA_kernel,
                         cudaFuncAttributeMaxDynamicSharedMemorySize, KA_SMEM_BYTES);
    cudaFuncSetAttribute(connB_kernel,
                         cudaFuncAttributeMaxDynamicSharedMemorySize, KB_SMEM_BYTES);

    connA_kernel<<<512, 128, KA_SMEM_BYTES>>>(x, v, W1, b1, W2, b2);
    connB_kernel<<<256, 256, KB_SMEM_BYTES>>>(v, W3, (float*)d_out);
}

// round 17
// speedup vs baseline: 2.0019x; 1.1944x over previous
#include <cuda_runtime.h>
#include <cstdint>

#define PAD_A 68
#define PAD_C 65
#define PAD_G 67

#define KA_SMEM_FLOATS (128*PAD_A + 64*PAD_A + 64*4)
#define KA_SMEM_BYTES (KA_SMEM_FLOATS * 4)

// connB: 2 systems per CTA
#define KB_SMEM_FLOATS (2*64*PAD_G + 128 + 2*128 + 2*64)
#define KB_SMEM_BYTES (KB_SMEM_FLOATS * 4)

static __device__ float g_Wsym[4096 * 64];  // Wsym[a][m] = W2[a][m] + W2[aT][m]
static __device__ float g_g[256][64][64];   // [n][i][r] = g[r][i]
static __device__ float g_w[512][64];       // per half-CTA partial w

__device__ __forceinline__ unsigned long long pk2(float x, float y) {
    unsigned long long r;
    asm("mov.b64 %0, {%1, %2};" : "=l"(r) : "f"(x), "f"(y));
    return r;
}
__device__ __forceinline__ void upk2(unsigned long long v, float &x, float &y) {
    asm("mov.b64 {%0, %1}, %2;" : "=f"(x), "=f"(y) : "l"(v));
}
__device__ __forceinline__ void fma2(unsigned long long &d, unsigned long long a, unsigned long long b) {
    asm("fma.rn.f32x2 %0, %1, %2, %0;" : "+l"(d) : "l"(a), "l"(b));
}
__device__ __forceinline__ uint32_t smem_u32(const void* p) {
    uint32_t a;
    asm("{ .reg .u64 t; cvta.to.shared.u64 t, %1; cvt.u32.u64 %0, t; }" : "=r"(a) : "l"(p));
    return a;
}
__device__ __forceinline__ void cpa16(uint32_t dst, const void* src) {
    asm volatile("cp.async.ca.shared.global [%0], [%1], 16;" :: "r"(dst), "l"(src));
}
#define CP_COMMIT() asm volatile("cp.async.commit_group;" ::: "memory")
#define CP_WAIT0()  asm volatile("cp.async.wait_group 0;" ::: "memory")

// ---------------- prep: Wsym = W2 + W2^T (over first index pair) ----------
__global__ void __launch_bounds__(256) prep_kernel(const float* __restrict__ W2) {
    const int e = (blockIdx.x * 256 + threadIdx.x) * 4;   // 256 blocks cover 4096*64
    const int a = e >> 6, m = e & 63;
    const int i = a >> 6, j = a & 63;
    float4 u = *(const float4*)(W2 + a * 64 + m);
    float4 w = *(const float4*)(W2 + (j * 64 + i) * 64 + m);
    u.x += w.x; u.y += w.y; u.z += w.z; u.w += w.w;
    *(float4*)(g_Wsym + a * 64 + m) = u;
}

// ---------------- kernel A: half-sample GEMM + w/g production -------------
__global__ void __launch_bounds__(128, 4) connA_kernel(
    const float* __restrict__ x, const float* __restrict__ v,
    const float* __restrict__ W1, const float* __restrict__ b1,
    const float* __restrict__ b2g)
{
    const int c    = blockIdx.x;
    const int n    = c >> 1;
    const int half = c & 1;
    const int t    = threadIdx.x;

    extern __shared__ float smem[];
    float* buf = smem;                 // overlay: A [128][PAD_A] / C [128][PAD_C]
    float* sB  = buf + 128 * PAD_A;    // [64][PAD_A]
    float* sh  = sB  + 64 * PAD_A;
    float* sv  = sh  + 64;
    float* sx  = sv  + 64;
    float* ssc = sx  + 64;
    const uint32_t buf_u32 = smem_u32(buf);

    // ---- load x, v ----
    if (t < 64) { sx[t] = x[n*64 + t]; sv[t] = v[n*64 + t]; }
    __syncthreads();

    // ---- h = tanh(W1 x + b1), s = 1 - h^2  (2 threads per row) ----
    const int m  = t >> 1;
    const int qq = t & 1;
    {
        const float4* w1r = (const float4*)(W1 + m*64 + qq*32);
        float p = 0.f;
        #pragma unroll
        for (int k = 0; k < 8; k++) {
            float4 wv = w1r[k];
            const float* xs = sx + qq*32 + k*4;
            p += wv.x*xs[0] + wv.y*xs[1] + wv.z*xs[2] + wv.w*xs[3];
        }
        p += __shfl_xor_sync(0xffffffffu, p, 1);
        if (qq == 0) {
            float hh = tanhf(p + b1[m]);
            sh[m]  = hh;
            ssc[m] = 1.f - hh*hh;
        }
    }
    __syncthreads();

    // ---- sB[m][l] = s[m] * W1[m][l] ----
    {
        const float sm_ = ssc[m];
        const float4* w1r = (const float4*)(W1 + m*64 + qq*32);
        float4* dst = (float4*)(sB + m*PAD_A + qq*32);
        #pragma unroll
        for (int k = 0; k < 8; k++) {
            float4 wv = w1r[k];
            wv.x *= sm_; wv.y *= sm_; wv.z *= sm_; wv.w *= sm_;
            dst[k] = wv;
        }
    }
    // (first group's stage sync orders sB before GEMM reads)

    float wacc[16];
    #pragma unroll
    for (int k = 0; k < 16; k++) wacc[k] = 0.f;

    const int tx = t & 7;        // GEMM col group
    const int ty = t >> 3;       // GEMM row base (0..15), rows ty + 16a
    const int ur = t >> 6;       // stage block (0..1)
    const int rr = t & 63;       // stage row
    const int j2 = t & 31;       // consume j base (j2, j2+32)
    const int pq = t >> 5;       // consume l-quarter (0..3)

    const float* bcol0 = sB + 4*tx;
    const float* arow0 = buf + ty*PAD_A;
    const uint32_t stage_dst = buf_u32 + (uint32_t)((ur*64 + rr)*PAD_A) * 4u;

    // ============ group loop: 2 bb blocks per iteration, 16 groups ============
    for (int g = 0; g < 16; ++g) {
        const int bb0 = half*32 + g*2;
        const int bb  = bb0 + ur;

        // ---- stage 2 Wsym blocks via cp.async (no register round-trip) ----
        {
            const float* src = g_Wsym + (bb*64 + rr)*64;
            #pragma unroll
            for (int k = 0; k < 16; ++k)
                cpa16(stage_dst + k*16u, src + k*4);
            CP_COMMIT();
            CP_WAIT0();
        }
        __syncthreads();

        // ---- g column from smem (conflict-free float4 row dot) ----
        {
            const float* arow = buf + (ur*64 + rr)*PAD_A;
            float gp = 0.f;
            #pragma unroll
            for (int k = 0; k < 16; ++k) {
                const float4 a4 = *(const float4*)(arow + 4*k);
                const float* hp = sh + 4*k;
                gp += a4.x*hp[0] + a4.y*hp[1] + a4.z*hp[2] + a4.w*hp[3];
            }
            g_g[n][bb][rr] = gp + b2g[bb*64 + rr] + b2g[rr*64 + bb];
        }

        // ---- GEMM: C(128x64) = A(128x64) @ B(64x64), 8x8 tile/thread ----
        unsigned long long acc[8][4];
        #pragma unroll
        for (int a = 0; a < 8; ++a) {
            acc[a][0] = 0ull; acc[a][1] = 0ull; acc[a][2] = 0ull; acc[a][3] = 0ull;
        }

        #pragma unroll 1
        for (int m2 = 0; m2 < 64; m2 += 2) {
            float2 av8[8];
            #pragma unroll
            for (int a = 0; a < 8; ++a)
                av8[a] = *(const float2*)(arow0 + (16*a)*PAD_A + m2);
            const float* b0p = bcol0 + m2*PAD_A;
            const ulonglong2 b0l = *(const ulonglong2*)(b0p);
            const ulonglong2 b0h = *(const ulonglong2*)(b0p + 32);
            const ulonglong2 b1l = *(const ulonglong2*)(b0p + PAD_A);
            const ulonglong2 b1h = *(const ulonglong2*)(b0p + PAD_A + 32);
            #pragma unroll
            for (int a = 0; a < 8; ++a) {
                const unsigned long long a0 = pk2(av8[a].x, av8[a].x);
                fma2(acc[a][0], a0, b0l.x);
                fma2(acc[a][1], a0, b0l.y);
                fma2(acc[a][2], a0, b0h.x);
                fma2(acc[a][3], a0, b0h.y);
                const unsigned long long a1 = pk2(av8[a].y, av8[a].y);
                fma2(acc[a][0], a1, b1l.x);
                fma2(acc[a][1], a1, b1l.y);
                fma2(acc[a][2], a1, b1h.x);
                fma2(acc[a][3], a1, b1h.y);
            }
        }
        __syncthreads();   // done reading buf-as-A

        // ---- store C into buf-as-C (pad 65) ----
        #pragma unroll
        for (int a = 0; a < 8; ++a) {
            float* crow = buf + (ty + 16*a)*PAD_C;
            float f0, f1;
            upk2(acc[a][0], f0, f1); crow[4*tx]      = f0; crow[4*tx + 1]      = f1;
            upk2(acc[a][1], f0, f1); crow[4*tx + 2]  = f0; crow[4*tx + 3]      = f1;
            upk2(acc[a][2], f0, f1); crow[32 + 4*tx] = f0; crow[32 + 4*tx + 1] = f1;
            upk2(acc[a][3], f0, f1); crow[32 + 4*tx + 2] = f0; crow[32 + 4*tx + 3] = f1;
        }
        __syncthreads();

        // ---- consume: thread = (j2, quarter pq); j in {j2, j2+32}, both blocks ----
        #pragma unroll
        for (int u = 0; u < 2; ++u) {
            const float vi = sv[bb0 + u];
            #pragma unroll
            for (int jh = 0; jh < 2; ++jh) {
                const int j = j2 + jh*32;
                const float coef = vi * sv[j];
                const float* crow = buf + (u*64 + j)*PAD_C;        // C[j][l]
                const float* ccol = buf + (u*64)*PAD_C + j;        // C[l][j] base
                #pragma unroll
                for (int k = 0; k < 16; ++k) {
                    const int l = pq*16 + k;
                    const float cc = crow[l];
                    const float ct = ccol[l*PAD_C];
                    wacc[k] += coef * cc * cc * ct;
                }
            }
        }
        __syncthreads();   // before next stage overwrites buf
    }

    // ---- reduce: scratch[j2][l], sum over j2, write partial w ----
    #pragma unroll
    for (int k = 0; k < 16; ++k) buf[j2*PAD_C + pq*16 + k] = wacc[k];
    __syncthreads();
    if (t < 64) {
        float s = 0.f;
        #pragma unroll 4
        for (int j = 0; j < 32; ++j) s += buf[j*PAD_C + t];
        g_w[c][t] = s;
    }
}

// ---------------- kernel B: assemble g, solve (2 samples/CTA), output -----
__global__ void __launch_bounds__(256, 4) connB_kernel(
    const float* __restrict__ v, const float* __restrict__ W3,
    float* __restrict__ out)
{
    const int n0 = blockIdx.x * 2;
    const int t  = threadIdx.x;

    extern __shared__ float smem[];
    float* sG  = smem;                  // [2][64][PAD_G], col 64 = rhs
    float* sf  = sG + 2*64*PAD_G;       // [128]
    float* sz  = sf + 128;              // [2][128]
    float* svv = sz + 2*128;            // [2][64]

    // load g: g_g[n][i][r] holds g[r][i]
    for (int idx = t; idx < 2*4096; idx += 256) {
        const int sys = idx >> 12;
        const int rem = idx & 4095;
        const int i = rem >> 6, r = rem & 63;
        sG[(sys*64 + r)*PAD_G + i] = g_g[n0 + sys][i][r];
    }
    if (t < 128) {
        const int sys = t >> 6, l = t & 63;
        sG[(sys*64 + l)*PAD_G + 64] = g_w[2*(n0+sys)][l] + g_w[2*(n0+sys) + 1][l];
        svv[t] = v[(n0+sys)*64 + l];
    }
    __syncthreads();

    // Gauss-Jordan, both systems in lockstep
    {
        const int sysu = t >> 7;            // update: system
        const int ru   = (t >> 1) & 63;     // update: row
        const int ch   = t & 1;             // update: col half
        const int cbeg = ch * 32;
        float* Gu = sG + sysu*64*PAD_G;
        for (int p = 0; p < 64; ++p) {
            if (t < 128) {
                const int sysf = t >> 6, rf = t & 63;
                const float* Gf = sG + sysf*64*PAD_G;
                const float piv = Gf[p*PAD_G + p];
                sf[t] = (rf == p) ? 0.f : Gf[rf*PAD_G + p] / piv;
            }
            __syncthreads();
            if (ru != p) {
                const float fr = sf[sysu*64 + ru];
                const float* prow = Gu + p*PAD_G;
                float* rrow = Gu + ru*PAD_G;
                #pragma unroll
                for (int cc = 0; cc < 32; ++cc)
                    rrow[cbeg + cc] -= fr * prow[cbeg + cc];
                if (ch)
                    rrow[64] -= fr * prow[64];
            }
            __syncthreads();
        }
    }

    if (t < 128) {
        const int sys = t >> 6, l = t & 63;
        const float* G = sG + sys*64*PAD_G;
        const float y = G[l*PAD_G + 64] / G[l*PAD_G + l];
        sz[sys*128 + l]      = svv[t];
        sz[sys*128 + 64 + l] = 0.5f * y;
    }
    __syncthreads();

    // out[n,k] = sum_c z[c] * W3[k,c]  (2 threads per output)
    {
        const int sys = t >> 7;
        const int k   = (t >> 1) & 63;
        const int qh  = t & 1;
        const float4* w3r = (const float4*)(W3 + k*128 + qh*64);
        const float* zz0 = sz + sys*128 + qh*64;
        float p = 0.f;
        #pragma unroll
        for (int j = 0; j < 16; ++j) {
            float4 wv = w3r[j];
            const float* zz = zz0 + j*4;
            p += wv.x*zz[0] + wv.y*zz[1] + wv.z*zz[2] + wv.w*zz[3];
        }
        p += __shfl_xor_sync(0xffffffffu, p, 1);
        if (qh == 0) out[(n0+sys)*64 + k] = p;
    }
}

extern "C" void kernel_launch(void* const* d_in, const int* in_sizes, int n_in,
                              void* d_out, int out_size)
{
    // inputs: 0:t (unused), 1:x (256*64), 2:v, 3:W1, 4:b1, 5:W2 (4096*64),
    //         6:b2 (4096), 7:W3 (64*128); output: (256,64) fp32
    const float* x  = (const float*)d_in[1];
    const float* v  = (const float*)d_in[2];
    const float* W1 = (const float*)d_in[3];
    const float* b1 = (const float*)d_in[4];
    const float* W2 = (const float*)d_in[5];
    const float* b2 = (const float*)d_in[6];
    const float* W3 = (const float*)d_in[7];

    cudaFuncSetAttribute(connA_kernel,
                         cudaFuncAttributeMaxDynamicSharedMemorySize, KA_SMEM_BYTES);
    cudaFuncSetAttribute(connB_kernel,
                         cudaFuncAttributeMaxDynamicSharedMemorySize, KB_SMEM_BYTES);

    prep_kernel<<<256, 256>>>(W2);
    connA_kernel<<<512, 128, KA_SMEM_BYTES>>>(x, v, W1, b1, b2);
    connB_kernel<<<128, 256, KB_SMEM_BYTES>>>(v, W3, (float*)d_out);
}